// round 3
// baseline (speedup 1.0000x reference)
#include <cuda_runtime.h>
#include <math.h>

// ---------------------------------------------------------------------------
// MemoryBankContrastLoss — full JAX-threefry-exact pipeline on GB300.
// Inputs: 0 main_proj f32[4,256,128,128], 1 main_gt i32[4,128,128],
//         2 aux_proj, 3 aux_gt, 4 ema_bank f32[20,512,256], 5 main_bank.
// Output: 1 float scalar.
// Convention everywhere: index u==0 -> main, u==1 -> ema.
// ---------------------------------------------------------------------------

#define NCLS 20
#define MEMB 512
#define MV   256
#define DIM  256
#define NANC 5120   // 20*256 anchors

// ------------------------------ scratch ------------------------------------
__device__ int   g_selidx[2][NCLS][MEMB];
__device__ int   g_ancidx[NCLS][MV];
__device__ int   g_perms [2][NCLS][MEMB];
__device__ int   g_samp  [2][NCLS][MV];
__device__ float g_selvec[2][NCLS*MEMB][DIM];
__device__ float g_anch  [NANC][DIM];
__device__ float g_bankS [2][NCLS*MEMB][DIM];
__device__ float g_con   [2][NANC][DIM];
__device__ float g_psum  [2][NCLS][DIM];
__device__ float g_part  [2][40][NANC];
__device__ float g_plp   [2][NANC];

// ------------------------------ threefry -----------------------------------
__host__ __device__ __forceinline__ void tf2x32(unsigned k0, unsigned k1,
                                                unsigned c0, unsigned c1,
                                                unsigned& o0, unsigned& o1) {
    unsigned ks0 = k0, ks1 = k1, ks2 = k0 ^ k1 ^ 0x1BD11BDAu;
    unsigned x0 = c0 + ks0, x1 = c1 + ks1;
#define TFRND(r) { x0 += x1; x1 = (x1 << r) | (x1 >> (32 - r)); x1 ^= x0; }
    TFRND(13) TFRND(15) TFRND(26) TFRND(6)   x0 += ks1; x1 += ks2 + 1u;
    TFRND(17) TFRND(29) TFRND(16) TFRND(24)  x0 += ks2; x1 += ks0 + 2u;
    TFRND(13) TFRND(15) TFRND(26) TFRND(6)   x0 += ks0; x1 += ks1 + 3u;
    TFRND(17) TFRND(29) TFRND(16) TFRND(24)  x0 += ks1; x1 += ks2 + 4u;
    TFRND(13) TFRND(15) TFRND(26) TFRND(6)   x0 += ks2; x1 += ks0 + 5u;
#undef TFRND
    o0 = x0; o1 = x1;
}

__host__ __device__ __forceinline__ unsigned tfx(unsigned k0, unsigned k1, unsigned ctr) {
    unsigned a, b;
    tf2x32(k0, k1, 0u, ctr, a, b);
    return a ^ b;   // partitionable random_bits: y0 ^ y1 at counter (0, flat)
}

// ------------------------------ helpers ------------------------------------
__device__ __forceinline__ float wred(float v) {
#pragma unroll
    for (int o = 16; o > 0; o >>= 1) v += __shfl_xor_sync(0xffffffffu, v, o);
    return v;
}

// in-smem bitonic sort, ascending, n power of two
__device__ __forceinline__ void bitonic(unsigned long long* a, int n, int tid, int nt) {
    for (int size = 2; size <= n; size <<= 1) {
        for (int stride = size >> 1; stride > 0; stride >>= 1) {
            __syncthreads();
            for (int i = tid; i < (n >> 1); i += nt) {
                int pos = 2 * i - (i & (stride - 1));
                bool up = ((pos & size) == 0);
                unsigned long long x = a[pos], y = a[pos + stride];
                if ((x > y) == up) { a[pos] = y; a[pos + stride] = x; }
            }
        }
    }
    __syncthreads();
}

// ---------------------------------------------------------------------------
// K1: per-(task,class) ordered top-k pixel selection.
// task 0: main update sel (N=65536, k=512, key k1_main)
// task 1: ema  update sel (N=65536, k=512, key k1_ema)
// task 2: anchors (N=131072, k=256, key ks[2])
// Ordering key = (bits>>9, idx) ascending  ==  top_k(-uniform) with ties.
// ---------------------------------------------------------------------------
__global__ void select_k(const int* __restrict__ mgt, const int* __restrict__ agt,
                         unsigned km0, unsigned km1,
                         unsigned ke0, unsigned ke1,
                         unsigned ka0, unsigned ka1) {
    int task = blockIdx.x / NCLS, c = blockIdx.x % NCLS;
    int N = (task == 2) ? 131072 : 65536;
    int k = (task == 2) ? MV : MEMB;
    unsigned K0 = (task == 0) ? km0 : (task == 1) ? ke0 : ka0;
    unsigned K1 = (task == 0) ? km1 : (task == 1) ? ke1 : ka1;

    __shared__ int hist[1024];
    __shared__ unsigned long long cand[2048];
    __shared__ int s_cnt, s_cut;
    int tid = threadIdx.x;

    for (int b = tid; b < 1024; b += 256) hist[b] = 0;
    __syncthreads();

    unsigned base = (unsigned)c * (unsigned)N;
    for (int i = tid; i < N; i += 256) {
        int l = (task == 0) ? mgt[i]
              : (task == 1) ? agt[i]
              : (i < 65536 ? mgt[i] : agt[i - 65536]);
        if (l == c) {
            unsigned bits = tfx(K0, K1, base + (unsigned)i);
            atomicAdd(&hist[bits >> 22], 1);   // bin on top 10 of the 23 mantissa bits
        }
    }
    __syncthreads();
    if (tid == 0) {
        int cum = 0, cut = 1023;
        for (int b = 0; b < 1024; b++) { cum += hist[b]; if (cum >= k) { cut = b; break; } }
        s_cut = cut; s_cnt = 0;
    }
    __syncthreads();
    unsigned cut = (unsigned)s_cut;
    for (int i = tid; i < N; i += 256) {
        int l = (task == 0) ? mgt[i]
              : (task == 1) ? agt[i]
              : (i < 65536 ? mgt[i] : agt[i - 65536]);
        if (l == c) {
            unsigned bits = tfx(K0, K1, base + (unsigned)i);
            if ((bits >> 22) <= cut) {
                int p = atomicAdd(&s_cnt, 1);
                if (p < 2048)
                    cand[p] = ((unsigned long long)(bits >> 9) << 32) | (unsigned)i;
            }
        }
    }
    __syncthreads();
    int cnt = min(s_cnt, 2048);
    for (int i = cnt + tid; i < 2048; i += 256) cand[i] = 0xFFFFFFFFFFFFFFFFull;
    bitonic(cand, 2048, tid, 256);
    for (int j = tid; j < k; j += 256) {
        int idx = (int)(cand[j] & 0xFFFFFFFFu);
        if (task == 2) g_ancidx[c][j] = idx;
        else           g_selidx[task][c][j] = idx;
    }
}

// ---------------------------------------------------------------------------
// K2: slot permutations: kk_c = TF(k2,(0,c)); sub = TF(kk_c,(0,1));
// stable sort 512 full-32-bit keys, perms[j] = index of j-th smallest.
// ---------------------------------------------------------------------------
__global__ void perm_k(unsigned k2m0, unsigned k2m1, unsigned k2e0, unsigned k2e1) {
    int u = blockIdx.x / NCLS, c = blockIdx.x % NCLS;
    unsigned a0, a1, b0, b1;
    tf2x32(u ? k2e0 : k2m0, u ? k2e1 : k2m1, 0u, (unsigned)c, a0, a1);
    tf2x32(a0, a1, 0u, 1u, b0, b1);
    __shared__ unsigned long long arr[512];
    int tid = threadIdx.x;
    for (int j = tid; j < 512; j += 256) {
        unsigned bits = tfx(b0, b1, (unsigned)j);
        arr[j] = ((unsigned long long)bits << 32) | (unsigned)j;
    }
    bitonic(arr, 512, tid, 256);
    for (int j = tid; j < 512; j += 256)
        g_perms[u][c][j] = (int)(arr[j] & 0xFFFFFFFFu);
}

// ---------------------------------------------------------------------------
// K3: bank sampling: top-256 of 512 slots by (u23, idx); all slots valid.
// ---------------------------------------------------------------------------
__global__ void samp_k(unsigned ksm0, unsigned ksm1, unsigned kse0, unsigned kse1) {
    int u = blockIdx.x / NCLS, c = blockIdx.x % NCLS;
    unsigned K0 = u ? kse0 : ksm0, K1 = u ? kse1 : ksm1;
    __shared__ unsigned long long arr[512];
    int tid = threadIdx.x;
    for (int j = tid; j < 512; j += 256) {
        unsigned bits = tfx(K0, K1, (unsigned)(c * 512 + j));
        arr[j] = ((unsigned long long)(bits >> 9) << 32) | (unsigned)j;
    }
    bitonic(arr, 512, tid, 256);
    for (int j = tid; j < MV; j += 256)
        g_samp[u][c][j] = (int)(arr[j] & 0xFFFFFFFFu);
}

// ---------------------------------------------------------------------------
// K4: copy input banks into writable scratch (inputs must stay untouched).
// ---------------------------------------------------------------------------
__global__ void copy_banks(const float4* __restrict__ mainb, const float4* __restrict__ emab) {
    const int n4 = NCLS * MEMB * DIM / 4;   // 655360
    float4* b0 = (float4*)&g_bankS[0][0][0];
    float4* b1 = (float4*)&g_bankS[1][0][0];
    for (int i = blockIdx.x * blockDim.x + threadIdx.x; i < n4; i += gridDim.x * blockDim.x) {
        b0[i] = mainb[i];
        b1[i] = emab[i];
    }
}

// ---------------------------------------------------------------------------
// K5: gather + L2-normalize selected pixel embeddings (warp per vector).
// warps [0,10240): main sel, [10240,20480): ema sel, [20480,25600): anchors.
// ---------------------------------------------------------------------------
__global__ void gather_norm(const float* __restrict__ mainp, const float* __restrict__ auxp) {
    int w = blockIdx.x * 8 + (threadIdx.x >> 5);
    int lane = threadIdx.x & 31;
    const float* src;
    float* dst;
    int pix;
    if (w < 10240)      { int c = w >> 9, j = w & 511;  pix = g_selidx[0][c][j]; src = mainp; dst = g_selvec[0][w]; }
    else if (w < 20480) { int q = w - 10240; int c = q >> 9, j = q & 511; pix = g_selidx[1][c][j]; src = auxp; dst = g_selvec[1][q]; }
    else                { int q = w - 20480; int c = q >> 8, j = q & 255; pix = g_ancidx[c][j];
                          if (pix < 65536) src = mainp; else { src = auxp; pix -= 65536; }
                          dst = g_anch[q]; }
    size_t b = (size_t)(pix >> 14), s = (size_t)(pix & 16383);
    const float* base = src + b * 4194304u + s;
    float v[8]; float ss = 0.f;
#pragma unroll
    for (int t = 0; t < 8; t++) {
        v[t] = base[(size_t)(lane + 32 * t) * 16384u];
        ss += v[t] * v[t];
    }
    ss = wred(ss);
    float inv = 1.f / fmaxf(sqrtf(ss), 1e-12f);
#pragma unroll
    for (int t = 0; t < 8; t++) dst[lane + 32 * t] = v[t] * inv;
}

// ---------------------------------------------------------------------------
// K6: EMA bank update: slot perms[c][j] <- l2norm(m*old + (1-m)*sel_j).
// ---------------------------------------------------------------------------
__global__ void update_k() {
    int w = blockIdx.x * 8 + (threadIdx.x >> 5);
    int lane = threadIdx.x & 31;
    int u = w / (NCLS * MEMB);
    int q = w % (NCLS * MEMB);
    int c = q >> 9, j = q & 511;
    int slot = g_perms[u][c][j];
    float m  = u ? 0.999f : 0.9f;
    float om = u ? 0.001f : 0.1f;
    float* row = g_bankS[u][c * MEMB + slot];
    const float* sv = g_selvec[u][q];
    float v[8]; float ss = 0.f;
#pragma unroll
    for (int t = 0; t < 8; t++) {
        int d = lane + 32 * t;
        float x = m * row[d] + om * sv[d];
        v[t] = x; ss += x * x;
    }
    ss = wred(ss);
    float inv = 1.f / fmaxf(sqrtf(ss), 1e-12f);
#pragma unroll
    for (int t = 0; t < 8; t++) row[lane + 32 * t] = v[t] * inv;
}

// ---------------------------------------------------------------------------
// K7: materialize contrast rows (256 sampled slots / class) contiguously.
// ---------------------------------------------------------------------------
__global__ void contrast_k() {
    int w = blockIdx.x * 8 + (threadIdx.x >> 5);
    int lane = threadIdx.x & 31;
    int u = w / NANC, q = w % NANC;
    int c = q >> 8, j = q & 255;
    const float* src = g_bankS[u][c * MEMB + g_samp[u][c][j]];
    float* dst = g_con[u][q];
#pragma unroll
    for (int t = 0; t < 8; t++) { int d = lane + 32 * t; dst[d] = src[d]; }
}

// ---------------------------------------------------------------------------
// K8: per-class positive-sum vectors (deterministic sequential sum).
// ---------------------------------------------------------------------------
__global__ void possum_k() {
    int u = blockIdx.x / NCLS, c = blockIdx.x % NCLS;
    int d = threadIdx.x;
    float s = 0.f;
    for (int j = 0; j < MV; j++) s += g_con[u][c * MV + j][d];
    g_psum[u][c][d] = s;
}

// ---------------------------------------------------------------------------
// K9: GEMM + fused exp-rowsum. 128x128 tile, 8x8/thread, K chunks of 16.
// S_partial[u][colTile][row] = sum_j exp(10 * a_row . c_j) over the tile cols.
// ---------------------------------------------------------------------------
__global__ void __launch_bounds__(256) gemm_lse() {
    int u = blockIdx.z;
    int rowBase = blockIdx.y * 128, colBase = blockIdx.x * 128;
    __shared__ float As[16][128];
    __shared__ float Bs[16][128];
    __shared__ float red[128][17];
    const float* A = &g_anch[0][0];
    const float* B = &g_con[u][0][0];
    int tid = threadIdx.x;
    int tx = tid & 15, ty = tid >> 4;
    float acc[8][8];
#pragma unroll
    for (int i = 0; i < 8; i++)
#pragma unroll
        for (int j = 0; j < 8; j++) acc[i][j] = 0.f;

    int r0 = tid >> 2;
    int kk = (tid & 3) << 2;
    for (int kc = 0; kc < 256; kc += 16) {
        float4 a0 = *(const float4*)(A + (size_t)(rowBase + r0) * 256 + kc + kk);
        float4 a1 = *(const float4*)(A + (size_t)(rowBase + r0 + 64) * 256 + kc + kk);
        float4 b0 = *(const float4*)(B + (size_t)(colBase + r0) * 256 + kc + kk);
        float4 b1 = *(const float4*)(B + (size_t)(colBase + r0 + 64) * 256 + kc + kk);
        __syncthreads();
        As[kk + 0][r0] = a0.x; As[kk + 1][r0] = a0.y; As[kk + 2][r0] = a0.z; As[kk + 3][r0] = a0.w;
        As[kk + 0][r0 + 64] = a1.x; As[kk + 1][r0 + 64] = a1.y; As[kk + 2][r0 + 64] = a1.z; As[kk + 3][r0 + 64] = a1.w;
        Bs[kk + 0][r0] = b0.x; Bs[kk + 1][r0] = b0.y; Bs[kk + 2][r0] = b0.z; Bs[kk + 3][r0] = b0.w;
        Bs[kk + 0][r0 + 64] = b1.x; Bs[kk + 1][r0 + 64] = b1.y; Bs[kk + 2][r0 + 64] = b1.z; Bs[kk + 3][r0 + 64] = b1.w;
        __syncthreads();
#pragma unroll
        for (int k = 0; k < 16; k++) {
            float ar[8], br[8];
            *(float4*)(ar)     = *(const float4*)&As[k][ty * 8];
            *(float4*)(ar + 4) = *(const float4*)&As[k][ty * 8 + 4];
            *(float4*)(br)     = *(const float4*)&Bs[k][tx * 8];
            *(float4*)(br + 4) = *(const float4*)&Bs[k][tx * 8 + 4];
#pragma unroll
            for (int i = 0; i < 8; i++)
#pragma unroll
                for (int j = 0; j < 8; j++)
                    acc[i][j] = fmaf(ar[i], br[j], acc[i][j]);
        }
    }
#pragma unroll
    for (int i = 0; i < 8; i++) {
        float s = 0.f;
#pragma unroll
        for (int j = 0; j < 8; j++) s += expf(acc[i][j] * 10.f);
        red[ty * 8 + i][tx] = s;
    }
    __syncthreads();
    if (tid < 128) {
        float s = 0.f;
#pragma unroll
        for (int t = 0; t < 16; t++) s += red[tid][t];
        g_part[u][blockIdx.x][rowBase + tid] = s;
    }
}

// ---------------------------------------------------------------------------
// K10: per-anchor plp = 10*posdot/256 - log(sum_partials). Warp per anchor.
// ---------------------------------------------------------------------------
__global__ void reduce_plp() {
    int w = blockIdx.x * 8 + (threadIdx.x >> 5);
    int lane = threadIdx.x & 31;
    int u = w / NANC, i = w % NANC;
    int c = i >> 8;
    float pd = 0.f;
#pragma unroll
    for (int t = 0; t < 8; t++) {
        int d = lane + 32 * t;
        pd += g_anch[i][d] * g_psum[u][c][d];
    }
    pd = wred(pd);
    float s = 0.f;
    for (int t = lane; t < 40; t += 32) s += g_part[u][t][i];
    s = wred(s);
    if (lane == 0)
        g_plp[u][i] = pd * (10.f / 256.f) - logf(s);
}

// ---------------------------------------------------------------------------
// K11: final scalar: loss = 0.5*(-mean plp_ema) + 0.5*(-mean plp_main)
//                        = -(sum over both)/10240.
// ---------------------------------------------------------------------------
__global__ void final_k(float* out) {
    __shared__ double sm[256];
    double s = 0.0;
    const float* p = &g_plp[0][0];
    for (int i = threadIdx.x; i < 2 * NANC; i += 256) s += (double)p[i];
    sm[threadIdx.x] = s;
    __syncthreads();
    for (int st = 128; st > 0; st >>= 1) {
        if (threadIdx.x < st) sm[threadIdx.x] += sm[threadIdx.x + st];
        __syncthreads();
    }
    if (threadIdx.x == 0) out[0] = (float)(-sm[0] / 10240.0);
}

// ---------------------------------------------------------------------------
extern "C" void kernel_launch(void* const* d_in, const int* in_sizes, int n_in,
                              void* d_out, int out_size) {
    (void)in_sizes; (void)n_in; (void)out_size;
    const float* main_proj = (const float*)d_in[0];
    const int*   main_gt   = (const int*)d_in[1];
    const float* aux_proj  = (const float*)d_in[2];
    const int*   aux_gt    = (const int*)d_in[3];
    const float* ema_bank  = (const float*)d_in[4];
    const float* main_bank = (const float*)d_in[5];
    float* out = (float*)d_out;

    // ---- host-side key chain (pure constants; threefry-partitionable) ----
    // key = jax.random.key(42) -> (hi=0, lo=42); ks[j] = TF(key,(0,j))
    unsigned ks[5][2];
    for (unsigned j = 0; j < 5; j++) tf2x32(0u, 42u, 0u, j, ks[j][0], ks[j][1]);
    unsigned k1m[2], k2m[2], k1e[2], k2e[2];
    tf2x32(ks[0][0], ks[0][1], 0u, 0u, k1m[0], k1m[1]);  // main update: select key
    tf2x32(ks[0][0], ks[0][1], 0u, 1u, k2m[0], k2m[1]);  // main update: perm key
    tf2x32(ks[1][0], ks[1][1], 0u, 0u, k1e[0], k1e[1]);  // ema update: select key
    tf2x32(ks[1][0], ks[1][1], 0u, 1u, k2e[0], k2e[1]);  // ema update: perm key
    // ks[2] = anchor select; ks[3] = ema bank sample; ks[4] = main bank sample

    select_k<<<60, 256>>>(main_gt, aux_gt,
                          k1m[0], k1m[1], k1e[0], k1e[1], ks[2][0], ks[2][1]);
    perm_k<<<40, 256>>>(k2m[0], k2m[1], k2e[0], k2e[1]);
    samp_k<<<40, 256>>>(ks[4][0], ks[4][1], ks[3][0], ks[3][1]);
    copy_banks<<<2560, 256>>>((const float4*)main_bank, (const float4*)ema_bank);
    gather_norm<<<3200, 256>>>(main_proj, aux_proj);
    update_k<<<2560, 256>>>();
    contrast_k<<<1280, 256>>>();
    possum_k<<<40, 256>>>();
    gemm_lse<<<dim3(40, 40, 2), 256>>>();
    reduce_plp<<<1280, 256>>>();
    final_k<<<1, 256>>>(out);
}

// round 9
// speedup vs baseline: 1.9064x; 1.9064x over previous
#include <cuda_runtime.h>
#include <cuda_fp16.h>
#include <cstdint>
#include <stdint.h>
#include <math.h>

// ---------------------------------------------------------------------------
// MemoryBankContrastLoss — JAX-threefry-exact pipeline, mma.sync (HMMA) GEMM.
// u==0 -> main, u==1 -> ema.
// ---------------------------------------------------------------------------

#define NCLS 20
#define MEMB 512
#define MV   256
#define DIM  256
#define NANC 5120   // 20*256 anchors
#define NTIL 40     // 5120/128 col tiles per GEMM dimension

// ------------------------------ scratch ------------------------------------
__device__ int   g_selidx[2][NCLS][MEMB];
__device__ int   g_ancidx[NCLS][MV];
__device__ int   g_perms [2][NCLS][MEMB];
__device__ int   g_samp  [2][NCLS][MV];
__device__ float g_selvec[2][NCLS*MEMB][DIM];
__device__ float g_anch  [NANC][DIM];
__device__ float g_bankS [2][NCLS*MEMB][DIM];
__device__ float g_con   [2][NANC][DIM];
__device__ float g_psum  [2][NCLS][DIM];
__device__ float g_part  [2][NTIL][NANC];
__device__ float g_plp   [2][NANC];

// fp16 copies for the tensor-core GEMM
__device__ __align__(16) __half g_A16[NANC*DIM];
__device__ __align__(16) __half g_B16[2][NANC*DIM];

// ------------------------------ threefry -----------------------------------
__host__ __device__ __forceinline__ void tf2x32(unsigned k0, unsigned k1,
                                                unsigned c0, unsigned c1,
                                                unsigned& o0, unsigned& o1) {
    unsigned ks0 = k0, ks1 = k1, ks2 = k0 ^ k1 ^ 0x1BD11BDAu;
    unsigned x0 = c0 + ks0, x1 = c1 + ks1;
#define TFRND(r) { x0 += x1; x1 = (x1 << r) | (x1 >> (32 - r)); x1 ^= x0; }
    TFRND(13) TFRND(15) TFRND(26) TFRND(6)   x0 += ks1; x1 += ks2 + 1u;
    TFRND(17) TFRND(29) TFRND(16) TFRND(24)  x0 += ks2; x1 += ks0 + 2u;
    TFRND(13) TFRND(15) TFRND(26) TFRND(6)   x0 += ks0; x1 += ks1 + 3u;
    TFRND(17) TFRND(29) TFRND(16) TFRND(24)  x0 += ks1; x1 += ks2 + 4u;
    TFRND(13) TFRND(15) TFRND(26) TFRND(6)   x0 += ks2; x1 += ks0 + 5u;
#undef TFRND
    o0 = x0; o1 = x1;
}

__host__ __device__ __forceinline__ unsigned tfx(unsigned k0, unsigned k1, unsigned ctr) {
    unsigned a, b;
    tf2x32(k0, k1, 0u, ctr, a, b);
    return a ^ b;
}

// ------------------------------ helpers ------------------------------------
__device__ __forceinline__ float wred(float v) {
#pragma unroll
    for (int o = 16; o > 0; o >>= 1) v += __shfl_xor_sync(0xffffffffu, v, o);
    return v;
}

__device__ __forceinline__ void bitonic(unsigned long long* a, int n, int tid, int nt) {
    for (int size = 2; size <= n; size <<= 1) {
        for (int stride = size >> 1; stride > 0; stride >>= 1) {
            __syncthreads();
            for (int i = tid; i < (n >> 1); i += nt) {
                int pos = 2 * i - (i & (stride - 1));
                bool up = ((pos & size) == 0);
                unsigned long long x = a[pos], y = a[pos + stride];
                if ((x > y) == up) { a[pos] = y; a[pos + stride] = x; }
            }
        }
    }
    __syncthreads();
}

__device__ __forceinline__ uint32_t smem_u32(const void* p) {
    uint32_t a;
    asm("{ .reg .u64 t; cvta.to.shared.u64 t, %1; cvt.u32.u64 %0, t; }" : "=r"(a) : "l"(p));
    return a;
}

// ---------------------------------------------------------------------------
// K1: per-(task,class) ordered top-k pixel selection.
// ---------------------------------------------------------------------------
__global__ void select_k(const int* __restrict__ mgt, const int* __restrict__ agt,
                         unsigned km0, unsigned km1,
                         unsigned ke0, unsigned ke1,
                         unsigned ka0, unsigned ka1) {
    int task = blockIdx.x / NCLS, c = blockIdx.x % NCLS;
    int N = (task == 2) ? 131072 : 65536;
    int k = (task == 2) ? MV : MEMB;
    unsigned K0 = (task == 0) ? km0 : (task == 1) ? ke0 : ka0;
    unsigned K1 = (task == 0) ? km1 : (task == 1) ? ke1 : ka1;

    __shared__ int hist[1024];
    __shared__ unsigned long long cand[2048];
    __shared__ int s_cnt, s_cut;
    int tid = threadIdx.x;

    for (int b = tid; b < 1024; b += 256) hist[b] = 0;
    __syncthreads();

    unsigned base = (unsigned)c * (unsigned)N;
    for (int i = tid; i < N; i += 256) {
        int l = (task == 0) ? mgt[i]
              : (task == 1) ? agt[i]
              : (i < 65536 ? mgt[i] : agt[i - 65536]);
        if (l == c) {
            unsigned bits = tfx(K0, K1, base + (unsigned)i);
            atomicAdd(&hist[bits >> 22], 1);
        }
    }
    __syncthreads();
    if (tid == 0) {
        int cum = 0, cut = 1023;
        for (int b = 0; b < 1024; b++) { cum += hist[b]; if (cum >= k) { cut = b; break; } }
        s_cut = cut; s_cnt = 0;
    }
    __syncthreads();
    unsigned cut = (unsigned)s_cut;
    for (int i = tid; i < N; i += 256) {
        int l = (task == 0) ? mgt[i]
              : (task == 1) ? agt[i]
              : (i < 65536 ? mgt[i] : agt[i - 65536]);
        if (l == c) {
            unsigned bits = tfx(K0, K1, base + (unsigned)i);
            if ((bits >> 22) <= cut) {
                int p = atomicAdd(&s_cnt, 1);
                if (p < 2048)
                    cand[p] = ((unsigned long long)(bits >> 9) << 32) | (unsigned)i;
            }
        }
    }
    __syncthreads();
    int cnt = min(s_cnt, 2048);
    for (int i = cnt + tid; i < 2048; i += 256) cand[i] = 0xFFFFFFFFFFFFFFFFull;
    bitonic(cand, 2048, tid, 256);
    for (int j = tid; j < k; j += 256) {
        int idx = (int)(cand[j] & 0xFFFFFFFFu);
        if (task == 2) g_ancidx[c][j] = idx;
        else           g_selidx[task][c][j] = idx;
    }
}

// ---------------------------------------------------------------------------
// K2: slot permutations.
// ---------------------------------------------------------------------------
__global__ void perm_k(unsigned k2m0, unsigned k2m1, unsigned k2e0, unsigned k2e1) {
    int u = blockIdx.x / NCLS, c = blockIdx.x % NCLS;
    unsigned a0, a1, b0, b1;
    tf2x32(u ? k2e0 : k2m0, u ? k2e1 : k2m1, 0u, (unsigned)c, a0, a1);
    tf2x32(a0, a1, 0u, 1u, b0, b1);
    __shared__ unsigned long long arr[512];
    int tid = threadIdx.x;
    for (int j = tid; j < 512; j += 256) {
        unsigned bits = tfx(b0, b1, (unsigned)j);
        arr[j] = ((unsigned long long)bits << 32) | (unsigned)j;
    }
    bitonic(arr, 512, tid, 256);
    for (int j = tid; j < 512; j += 256)
        g_perms[u][c][j] = (int)(arr[j] & 0xFFFFFFFFu);
}

// ---------------------------------------------------------------------------
// K3: bank sampling.
// ---------------------------------------------------------------------------
__global__ void samp_k(unsigned ksm0, unsigned ksm1, unsigned kse0, unsigned kse1) {
    int u = blockIdx.x / NCLS, c = blockIdx.x % NCLS;
    unsigned K0 = u ? kse0 : ksm0, K1 = u ? kse1 : ksm1;
    __shared__ unsigned long long arr[512];
    int tid = threadIdx.x;
    for (int j = tid; j < 512; j += 256) {
        unsigned bits = tfx(K0, K1, (unsigned)(c * 512 + j));
        arr[j] = ((unsigned long long)(bits >> 9) << 32) | (unsigned)j;
    }
    bitonic(arr, 512, tid, 256);
    for (int j = tid; j < MV; j += 256)
        g_samp[u][c][j] = (int)(arr[j] & 0xFFFFFFFFu);
}

// ---------------------------------------------------------------------------
// K4: copy input banks into writable scratch.
// ---------------------------------------------------------------------------
__global__ void copy_banks(const float4* __restrict__ mainb, const float4* __restrict__ emab) {
    const int n4 = NCLS * MEMB * DIM / 4;
    float4* b0 = (float4*)&g_bankS[0][0][0];
    float4* b1 = (float4*)&g_bankS[1][0][0];
    for (int i = blockIdx.x * blockDim.x + threadIdx.x; i < n4; i += gridDim.x * blockDim.x) {
        b0[i] = mainb[i];
        b1[i] = emab[i];
    }
}

// ---------------------------------------------------------------------------
// K5: gather + L2-normalize selected pixel embeddings (warp per vector).
// ---------------------------------------------------------------------------
__global__ void gather_norm(const float* __restrict__ mainp, const float* __restrict__ auxp) {
    int w = blockIdx.x * 8 + (threadIdx.x >> 5);
    int lane = threadIdx.x & 31;
    const float* src;
    float* dst;
    int pix;
    if (w < 10240)      { int c = w >> 9, j = w & 511;  pix = g_selidx[0][c][j]; src = mainp; dst = g_selvec[0][w]; }
    else if (w < 20480) { int q = w - 10240; int c = q >> 9, j = q & 511; pix = g_selidx[1][c][j]; src = auxp; dst = g_selvec[1][q]; }
    else                { int q = w - 20480; int c = q >> 8, j = q & 255; pix = g_ancidx[c][j];
                          if (pix < 65536) src = mainp; else { src = auxp; pix -= 65536; }
                          dst = g_anch[q]; }
    size_t b = (size_t)(pix >> 14), s = (size_t)(pix & 16383);
    const float* base = src + b * 4194304u + s;
    float v[8]; float ss = 0.f;
#pragma unroll
    for (int t = 0; t < 8; t++) {
        v[t] = base[(size_t)(lane + 32 * t) * 16384u];
        ss += v[t] * v[t];
    }
    ss = wred(ss);
    float inv = 1.f / fmaxf(sqrtf(ss), 1e-12f);
#pragma unroll
    for (int t = 0; t < 8; t++) dst[lane + 32 * t] = v[t] * inv;
}

// ---------------------------------------------------------------------------
// K6: EMA bank update.
// ---------------------------------------------------------------------------
__global__ void update_k() {
    int w = blockIdx.x * 8 + (threadIdx.x >> 5);
    int lane = threadIdx.x & 31;
    int u = w / (NCLS * MEMB);
    int q = w % (NCLS * MEMB);
    int c = q >> 9, j = q & 511;
    int slot = g_perms[u][c][j];
    float m  = u ? 0.999f : 0.9f;
    float om = u ? 0.001f : 0.1f;
    float* row = g_bankS[u][c * MEMB + slot];
    const float* sv = g_selvec[u][q];
    float v[8]; float ss = 0.f;
#pragma unroll
    for (int t = 0; t < 8; t++) {
        int d = lane + 32 * t;
        float x = m * row[d] + om * sv[d];
        v[t] = x; ss += x * x;
    }
    ss = wred(ss);
    float inv = 1.f / fmaxf(sqrtf(ss), 1e-12f);
#pragma unroll
    for (int t = 0; t < 8; t++) row[lane + 32 * t] = v[t] * inv;
}

// ---------------------------------------------------------------------------
// K7: materialize contrast rows.
// ---------------------------------------------------------------------------
__global__ void contrast_k() {
    int w = blockIdx.x * 8 + (threadIdx.x >> 5);
    int lane = threadIdx.x & 31;
    int u = w / NANC, q = w % NANC;
    int c = q >> 8, j = q & 255;
    const float* src = g_bankS[u][c * MEMB + g_samp[u][c][j]];
    float* dst = g_con[u][q];
#pragma unroll
    for (int t = 0; t < 8; t++) { int d = lane + 32 * t; dst[d] = src[d]; }
}

// ---------------------------------------------------------------------------
// K7b: fp16 conversion of anchors + contrast rows.
// ---------------------------------------------------------------------------
__global__ void conv_f16() {
    const int n1 = NANC * DIM;
    int stride = gridDim.x * blockDim.x;
    for (int i = blockIdx.x * blockDim.x + threadIdx.x; i < 3 * n1; i += stride) {
        int r = i / n1, j = i - r * n1;
        float x = (r == 0) ? (&g_anch[0][0])[j] : (&g_con[r - 1][0][0])[j];
        if (r == 0) g_A16[j] = __float2half(x);
        else        g_B16[r - 1][j] = __float2half(x);
    }
}

// ---------------------------------------------------------------------------
// K8: per-class positive-sum vectors.
// ---------------------------------------------------------------------------
__global__ void possum_k() {
    int u = blockIdx.x / NCLS, c = blockIdx.x % NCLS;
    int d = threadIdx.x;
    float s = 0.f;
    for (int j = 0; j < MV; j++) s += g_con[u][c * MV + j][d];
    g_psum[u][c][d] = s;
}

// ---------------------------------------------------------------------------
// K9: mma.sync fp16 GEMM + fused exp-rowsum.
// CTA: 128x128 tile, 8 warps (2m x 4n), each warp 64x32.
// K in 4 chunks of 64, 2-stage cp.async double buffer.
// smem rows padded to 72 halves (144B = 9*16B -> conflict-free ldmatrix).
// ---------------------------------------------------------------------------
#define KC 64
#define ROWP 72                       // halves per padded row
#define TILE_H (128 * ROWP)           // halves per tile (one matrix, one stage)
#define GEMM_SMEM (4 * TILE_H * 2)    // bytes: 2 matrices x 2 stages

__device__ __forceinline__ void ldsm_x4(uint32_t addr, uint32_t* r) {
    asm volatile("ldmatrix.sync.aligned.m8n8.x4.shared.b16 {%0,%1,%2,%3}, [%4];"
                 : "=r"(r[0]), "=r"(r[1]), "=r"(r[2]), "=r"(r[3]) : "r"(addr));
}
__device__ __forceinline__ void ldsm_x2(uint32_t addr, uint32_t* r) {
    asm volatile("ldmatrix.sync.aligned.m8n8.x2.shared.b16 {%0,%1}, [%2];"
                 : "=r"(r[0]), "=r"(r[1]) : "r"(addr));
}
__device__ __forceinline__ void mma16816(float* c, const uint32_t* a, const uint32_t* b) {
    asm volatile(
        "mma.sync.aligned.m16n8k16.row.col.f32.f16.f16.f32 "
        "{%0,%1,%2,%3}, {%4,%5,%6,%7}, {%8,%9}, {%0,%1,%2,%3};"
        : "+f"(c[0]), "+f"(c[1]), "+f"(c[2]), "+f"(c[3])
        : "r"(a[0]), "r"(a[1]), "r"(a[2]), "r"(a[3]), "r"(b[0]), "r"(b[1]));
}

// load one 128x64 fp16 tile into padded smem via cp.async (16B segments)
__device__ __forceinline__ void load_tile(uint32_t dbase, const __half* __restrict__ src,
                                          int gRowBase, int kc, int tid) {
#pragma unroll
    for (int r = 0; r < 4; r++) {
        int s = tid + r * 256;          // 0..1023
        int row = s >> 3;
        int c16 = s & 7;
        const __half* g = src + (size_t)(gRowBase + row) * DIM + kc * KC + c16 * 8;
        uint32_t d = dbase + row * (ROWP * 2) + c16 * 16;
        asm volatile("cp.async.cg.shared.global [%0], [%1], 16;" :: "r"(d), "l"(g) : "memory");
    }
}

__global__ void __launch_bounds__(256) gemm_mma() {
    extern __shared__ __half smh[];
    uint32_t sbase = smem_u32(smh);
    __shared__ float red[128][5];

    const int u = blockIdx.z;
    const int rowBase = blockIdx.y * 128;
    const int colBase = blockIdx.x * 128;
    int tid = threadIdx.x, w = tid >> 5, lane = tid & 31;
    int wm = w >> 2, wn = w & 3;           // warp 2x4 grid

    uint32_t uA[2] = { sbase,                sbase + (uint32_t)(TILE_H * 2) };
    uint32_t uB[2] = { sbase + (uint32_t)(2 * TILE_H * 2), sbase + (uint32_t)(3 * TILE_H * 2) };

    const __half* A = g_A16;
    const __half* B = g_B16[u];

    float c[4][4][4];
#pragma unroll
    for (int mt = 0; mt < 4; mt++)
#pragma unroll
        for (int nt = 0; nt < 4; nt++)
#pragma unroll
            for (int e = 0; e < 4; e++) c[mt][nt][e] = 0.f;

    load_tile(uA[0], A, rowBase, 0, tid);
    load_tile(uB[0], B, colBase, 0, tid);
    asm volatile("cp.async.commit_group;" ::: "memory");
    load_tile(uA[1], A, rowBase, 1, tid);
    load_tile(uB[1], B, colBase, 1, tid);
    asm volatile("cp.async.commit_group;" ::: "memory");

    // precomputed lane pieces for fragment addressing
    int aRow = wm * 64 + (lane & 15);
    int aColOff = ((lane >> 4) << 3);
    int bRow = wn * 32 + (lane & 7);
    int bColOff = (((lane >> 3) & 1) << 3);

#pragma unroll
    for (int i = 0; i < 4; i++) {
        if (i < 3) asm volatile("cp.async.wait_group 1;" ::: "memory");
        else       asm volatile("cp.async.wait_group 0;" ::: "memory");
        __syncthreads();
        const int st = i & 1;
#pragma unroll
        for (int kk = 0; kk < 4; kk++) {
            uint32_t a[4][4], b[4][2];
#pragma unroll
            for (int mt = 0; mt < 4; mt++) {
                uint32_t addr = uA[st] + (uint32_t)((aRow + mt * 16) * (ROWP * 2)
                              + (kk * 16 + aColOff) * 2);
                ldsm_x4(addr, a[mt]);
            }
#pragma unroll
            for (int nt = 0; nt < 4; nt++) {
                uint32_t addr = uB[st] + (uint32_t)((bRow + nt * 8) * (ROWP * 2)
                              + (kk * 16 + bColOff) * 2);
                ldsm_x2(addr, b[nt]);
            }
#pragma unroll
            for (int mt = 0; mt < 4; mt++)
#pragma unroll
                for (int nt = 0; nt < 4; nt++)
                    mma16816(c[mt][nt], a[mt], b[nt]);
        }
        __syncthreads();
        if (i + 2 < 4) {
            load_tile(uA[st], A, rowBase, i + 2, tid);
            load_tile(uB[st], B, colBase, i + 2, tid);
            asm volatile("cp.async.commit_group;" ::: "memory");
        } else {
            asm volatile("cp.async.commit_group;" ::: "memory");
        }
    }

    // epilogue: per-row sum of exp(10*d) over this CTA's 128 columns
#pragma unroll
    for (int mt = 0; mt < 4; mt++) {
        float s0 = 0.f, s1 = 0.f;
#pragma unroll
        for (int nt = 0; nt < 4; nt++) {
            s0 += __expf(10.f * c[mt][nt][0]) + __expf(10.f * c[mt][nt][1]);
            s1 += __expf(10.f * c[mt][nt][2]) + __expf(10.f * c[mt][nt][3]);
        }
        s0 += __shfl_xor_sync(0xffffffffu, s0, 1);
        s0 += __shfl_xor_sync(0xffffffffu, s0, 2);
        s1 += __shfl_xor_sync(0xffffffffu, s1, 1);
        s1 += __shfl_xor_sync(0xffffffffu, s1, 2);
        if ((lane & 3) == 0) {
            int r0 = wm * 64 + mt * 16 + (lane >> 2);
            red[r0][wn] = s0;
            red[r0 + 8][wn] = s1;
        }
    }
    __syncthreads();
    if (tid < 128) {
        float s = red[tid][0] + red[tid][1] + red[tid][2] + red[tid][3];
        g_part[u][blockIdx.x][rowBase + tid] = s;
    }
}

// ---------------------------------------------------------------------------
// K10: per-anchor plp = 10*posdot/256 - log(sum_partials). Warp per anchor.
// ---------------------------------------------------------------------------
__global__ void reduce_plp() {
    int w = blockIdx.x * 8 + (threadIdx.x >> 5);
    int lane = threadIdx.x & 31;
    int u = w / NANC, i = w % NANC;
    int c = i >> 8;
    float pd = 0.f;
#pragma unroll
    for (int t = 0; t < 8; t++) {
        int d = lane + 32 * t;
        pd += g_anch[i][d] * g_psum[u][c][d];
    }
    pd = wred(pd);
    float s = 0.f;
    for (int t = lane; t < NTIL; t += 32) s += g_part[u][t][i];
    s = wred(s);
    if (lane == 0)
        g_plp[u][i] = pd * (10.f / 256.f) - logf(s);
}

// ---------------------------------------------------------------------------
// K11: final scalar.
// ---------------------------------------------------------------------------
__global__ void final_k(float* out) {
    __shared__ double sm[256];
    double s = 0.0;
    const float* p = &g_plp[0][0];
    for (int i = threadIdx.x; i < 2 * NANC; i += 256) s += (double)p[i];
    sm[threadIdx.x] = s;
    __syncthreads();
    for (int st = 128; st > 0; st >>= 1) {
        if (threadIdx.x < st) sm[threadIdx.x] += sm[threadIdx.x + st];
        __syncthreads();
    }
    if (threadIdx.x == 0) out[0] = (float)(-sm[0] / 10240.0);
}

// ---------------------------------------------------------------------------
extern "C" void kernel_launch(void* const* d_in, const int* in_sizes, int n_in,
                              void* d_out, int out_size) {
    (void)in_sizes; (void)n_in; (void)out_size;
    const float* main_proj = (const float*)d_in[0];
    const int*   main_gt   = (const int*)d_in[1];
    const float* aux_proj  = (const float*)d_in[2];
    const int*   aux_gt    = (const int*)d_in[3];
    const float* ema_bank  = (const float*)d_in[4];
    const float* main_bank = (const float*)d_in[5];
    float* out = (float*)d_out;

    unsigned ks[5][2];
    for (unsigned j = 0; j < 5; j++) tf2x32(0u, 42u, 0u, j, ks[j][0], ks[j][1]);
    unsigned k1m[2], k2m[2], k1e[2], k2e[2];
    tf2x32(ks[0][0], ks[0][1], 0u, 0u, k1m[0], k1m[1]);
    tf2x32(ks[0][0], ks[0][1], 0u, 1u, k2m[0], k2m[1]);
    tf2x32(ks[1][0], ks[1][1], 0u, 0u, k1e[0], k1e[1]);
    tf2x32(ks[1][0], ks[1][1], 0u, 1u, k2e[0], k2e[1]);

    cudaFuncSetAttribute(gemm_mma, cudaFuncAttributeMaxDynamicSharedMemorySize, GEMM_SMEM);

    select_k<<<60, 256>>>(main_gt, aux_gt,
                          k1m[0], k1m[1], k1e[0], k1e[1], ks[2][0], ks[2][1]);
    perm_k<<<40, 256>>>(k2m[0], k2m[1], k2e[0], k2e[1]);
    samp_k<<<40, 256>>>(ks[4][0], ks[4][1], ks[3][0], ks[3][1]);
    copy_banks<<<2560, 256>>>((const float4*)main_bank, (const float4*)ema_bank);
    gather_norm<<<3200, 256>>>(main_proj, aux_proj);
    update_k<<<2560, 256>>>();
    contrast_k<<<1280, 256>>>();
    conv_f16<<<3840, 256>>>();
    possum_k<<<40, 256>>>();
    gemm_mma<<<dim3(NTIL, NTIL, 2), 256, GEMM_SMEM>>>();
    reduce_plp<<<1280, 256>>>();
    final_k<<<1, 256>>>(out);
}

// round 10
// speedup vs baseline: 3.8539x; 2.0215x over previous
#include <cuda_runtime.h>
#include <cuda_fp16.h>
#include <cstdint>
#include <stdint.h>
#include <math.h>

// ---------------------------------------------------------------------------
// MemoryBankContrastLoss — JAX-threefry-exact pipeline, mma.sync (HMMA) GEMM.
// u==0 -> main, u==1 -> ema.
// ---------------------------------------------------------------------------

#define NCLS 20
#define MEMB 512
#define MV   256
#define DIM  256
#define NANC 5120   // 20*256 anchors
#define NTIL 40     // 5120/128 col tiles per GEMM dimension

// ------------------------------ scratch ------------------------------------
__device__ int   g_selidx[2][NCLS][MEMB];
__device__ int   g_ancidx[NCLS][MV];
__device__ int   g_perms [2][NCLS][MEMB];
__device__ int   g_samp  [2][NCLS][MV];
__device__ float g_selvec[2][NCLS*MEMB][DIM];
__device__ float g_anch  [NANC][DIM];
__device__ float g_bankS [2][NCLS*MEMB][DIM];
__device__ float g_con   [2][NANC][DIM];
__device__ float g_psum  [2][NCLS][DIM];
__device__ float g_part  [2][NTIL][NANC];
__device__ float g_plp   [2][NANC];

// fp16 copies for the tensor-core GEMM
__device__ __align__(16) __half g_A16[NANC*DIM];
__device__ __align__(16) __half g_B16[2][NANC*DIM];

// ------------------------------ threefry -----------------------------------
__host__ __device__ __forceinline__ void tf2x32(unsigned k0, unsigned k1,
                                                unsigned c0, unsigned c1,
                                                unsigned& o0, unsigned& o1) {
    unsigned ks0 = k0, ks1 = k1, ks2 = k0 ^ k1 ^ 0x1BD11BDAu;
    unsigned x0 = c0 + ks0, x1 = c1 + ks1;
#define TFRND(r) { x0 += x1; x1 = (x1 << r) | (x1 >> (32 - r)); x1 ^= x0; }
    TFRND(13) TFRND(15) TFRND(26) TFRND(6)   x0 += ks1; x1 += ks2 + 1u;
    TFRND(17) TFRND(29) TFRND(16) TFRND(24)  x0 += ks2; x1 += ks0 + 2u;
    TFRND(13) TFRND(15) TFRND(26) TFRND(6)   x0 += ks0; x1 += ks1 + 3u;
    TFRND(17) TFRND(29) TFRND(16) TFRND(24)  x0 += ks1; x1 += ks2 + 4u;
    TFRND(13) TFRND(15) TFRND(26) TFRND(6)   x0 += ks2; x1 += ks0 + 5u;
#undef TFRND
    o0 = x0; o1 = x1;
}

__host__ __device__ __forceinline__ unsigned tfx(unsigned k0, unsigned k1, unsigned ctr) {
    unsigned a, b;
    tf2x32(k0, k1, 0u, ctr, a, b);
    return a ^ b;
}

// ------------------------------ helpers ------------------------------------
__device__ __forceinline__ float wred(float v) {
#pragma unroll
    for (int o = 16; o > 0; o >>= 1) v += __shfl_xor_sync(0xffffffffu, v, o);
    return v;
}

__device__ __forceinline__ void bitonic(unsigned long long* a, int n, int tid, int nt) {
    for (int size = 2; size <= n; size <<= 1) {
        for (int stride = size >> 1; stride > 0; stride >>= 1) {
            __syncthreads();
            for (int i = tid; i < (n >> 1); i += nt) {
                int pos = 2 * i - (i & (stride - 1));
                bool up = ((pos & size) == 0);
                unsigned long long x = a[pos], y = a[pos + stride];
                if ((x > y) == up) { a[pos] = y; a[pos + stride] = x; }
            }
        }
    }
    __syncthreads();
}

__device__ __forceinline__ uint32_t smem_u32(const void* p) {
    uint32_t a;
    asm("{ .reg .u64 t; cvta.to.shared.u64 t, %1; cvt.u32.u64 %0, t; }" : "=r"(a) : "l"(p));
    return a;
}

// ---------------------------------------------------------------------------
// K1: per-(task,class) ordered top-k pixel selection. 1024 threads, int4 scan.
// ---------------------------------------------------------------------------
__global__ void __launch_bounds__(1024) select_k(
        const int* __restrict__ mgt, const int* __restrict__ agt,
        unsigned km0, unsigned km1,
        unsigned ke0, unsigned ke1,
        unsigned ka0, unsigned ka1) {
    int task = blockIdx.x / NCLS, c = blockIdx.x % NCLS;
    int N = (task == 2) ? 131072 : 65536;
    int k = (task == 2) ? MV : MEMB;
    unsigned K0 = (task == 0) ? km0 : (task == 1) ? ke0 : ka0;
    unsigned K1 = (task == 0) ? km1 : (task == 1) ? ke1 : ka1;

    __shared__ int hist[1024];
    __shared__ unsigned long long cand[2048];
    __shared__ int s_cnt, s_cut;
    int tid = threadIdx.x;

    hist[tid] = 0;
    __syncthreads();

    unsigned base = (unsigned)c * (unsigned)N;
    int iters = N >> 12;   // N / 4096
    for (int it = 0; it < iters; it++) {
        int i0 = (it << 12) + (tid << 2);
        const int* src = (task == 0) ? mgt : (task == 1) ? agt
                       : (i0 < 65536 ? mgt : agt);
        int off = (task == 2 && i0 >= 65536) ? i0 - 65536 : i0;
        int4 l4 = *(const int4*)(src + off);
        int ls[4] = { l4.x, l4.y, l4.z, l4.w };
#pragma unroll
        for (int j = 0; j < 4; j++) {
            if (ls[j] == c) {
                unsigned bits = tfx(K0, K1, base + (unsigned)(i0 + j));
                atomicAdd(&hist[bits >> 22], 1);
            }
        }
    }
    __syncthreads();
    if (tid == 0) {
        int cum = 0, cut = 1023;
        for (int b = 0; b < 1024; b++) { cum += hist[b]; if (cum >= k) { cut = b; break; } }
        s_cut = cut; s_cnt = 0;
    }
    __syncthreads();
    unsigned cut = (unsigned)s_cut;
    for (int it = 0; it < iters; it++) {
        int i0 = (it << 12) + (tid << 2);
        const int* src = (task == 0) ? mgt : (task == 1) ? agt
                       : (i0 < 65536 ? mgt : agt);
        int off = (task == 2 && i0 >= 65536) ? i0 - 65536 : i0;
        int4 l4 = *(const int4*)(src + off);
        int ls[4] = { l4.x, l4.y, l4.z, l4.w };
#pragma unroll
        for (int j = 0; j < 4; j++) {
            if (ls[j] == c) {
                unsigned bits = tfx(K0, K1, base + (unsigned)(i0 + j));
                if ((bits >> 22) <= cut) {
                    int p = atomicAdd(&s_cnt, 1);
                    if (p < 2048)
                        cand[p] = ((unsigned long long)(bits >> 9) << 32) | (unsigned)(i0 + j);
                }
            }
        }
    }
    __syncthreads();
    int cnt = min(s_cnt, 2048);
    for (int i = cnt + tid; i < 2048; i += 1024) cand[i] = 0xFFFFFFFFFFFFFFFFull;
    bitonic(cand, 2048, tid, 1024);
    for (int j = tid; j < k; j += 1024) {
        int idx = (int)(cand[j] & 0xFFFFFFFFu);
        if (task == 2) g_ancidx[c][j] = idx;
        else           g_selidx[task][c][j] = idx;
    }
}

// ---------------------------------------------------------------------------
// K2: slot permutations.
// ---------------------------------------------------------------------------
__global__ void perm_k(unsigned k2m0, unsigned k2m1, unsigned k2e0, unsigned k2e1) {
    int u = blockIdx.x / NCLS, c = blockIdx.x % NCLS;
    unsigned a0, a1, b0, b1;
    tf2x32(u ? k2e0 : k2m0, u ? k2e1 : k2m1, 0u, (unsigned)c, a0, a1);
    tf2x32(a0, a1, 0u, 1u, b0, b1);
    __shared__ unsigned long long arr[512];
    int tid = threadIdx.x;
    for (int j = tid; j < 512; j += 256) {
        unsigned bits = tfx(b0, b1, (unsigned)j);
        arr[j] = ((unsigned long long)bits << 32) | (unsigned)j;
    }
    bitonic(arr, 512, tid, 256);
    for (int j = tid; j < 512; j += 256)
        g_perms[u][c][j] = (int)(arr[j] & 0xFFFFFFFFu);
}

// ---------------------------------------------------------------------------
// K3: bank sampling.
// ---------------------------------------------------------------------------
__global__ void samp_k(unsigned ksm0, unsigned ksm1, unsigned kse0, unsigned kse1) {
    int u = blockIdx.x / NCLS, c = blockIdx.x % NCLS;
    unsigned K0 = u ? kse0 : ksm0, K1 = u ? kse1 : ksm1;
    __shared__ unsigned long long arr[512];
    int tid = threadIdx.x;
    for (int j = tid; j < 512; j += 256) {
        unsigned bits = tfx(K0, K1, (unsigned)(c * 512 + j));
        arr[j] = ((unsigned long long)(bits >> 9) << 32) | (unsigned)j;
    }
    bitonic(arr, 512, tid, 256);
    for (int j = tid; j < MV; j += 256)
        g_samp[u][c][j] = (int)(arr[j] & 0xFFFFFFFFu);
}

// ---------------------------------------------------------------------------
// K5: gather + L2-normalize selected pixel embeddings (warp per vector).
// Anchors additionally written as fp16 for the GEMM.
// ---------------------------------------------------------------------------
__global__ void gather_norm(const float* __restrict__ mainp, const float* __restrict__ auxp) {
    int w = blockIdx.x * 8 + (threadIdx.x >> 5);
    int lane = threadIdx.x & 31;
    const float* src;
    float* dst;
    __half* dst16 = 0;
    int pix;
    if (w < 10240)      { int c = w >> 9, j = w & 511;  pix = g_selidx[0][c][j]; src = mainp; dst = g_selvec[0][w]; }
    else if (w < 20480) { int q = w - 10240; int c = q >> 9, j = q & 511; pix = g_selidx[1][c][j]; src = auxp; dst = g_selvec[1][q]; }
    else                { int q = w - 20480; int c = q >> 8, j = q & 255; pix = g_ancidx[c][j];
                          if (pix < 65536) src = mainp; else { src = auxp; pix -= 65536; }
                          dst = g_anch[q]; dst16 = &g_A16[q * DIM]; }
    size_t b = (size_t)(pix >> 14), s = (size_t)(pix & 16383);
    const float* base = src + b * 4194304u + s;
    float v[8]; float ss = 0.f;
#pragma unroll
    for (int t = 0; t < 8; t++) {
        v[t] = base[(size_t)(lane + 32 * t) * 16384u];
        ss += v[t] * v[t];
    }
    ss = wred(ss);
    float inv = 1.f / fmaxf(sqrtf(ss), 1e-12f);
#pragma unroll
    for (int t = 0; t < 8; t++) {
        float x = v[t] * inv;
        dst[lane + 32 * t] = x;
        if (dst16) dst16[lane + 32 * t] = __float2half(x);
    }
}

// ---------------------------------------------------------------------------
// K6: EMA bank update. Reads OLD values from the input banks (perm covers all
// 512 slots, so every row of g_bankS is produced here; no pre-copy needed).
// ---------------------------------------------------------------------------
__global__ void update_k(const float* __restrict__ mainb, const float* __restrict__ emab) {
    int w = blockIdx.x * 8 + (threadIdx.x >> 5);
    int lane = threadIdx.x & 31;
    int u = w / (NCLS * MEMB);
    int q = w % (NCLS * MEMB);
    int c = q >> 9, j = q & 511;
    int slot = g_perms[u][c][j];
    float m  = u ? 0.999f : 0.9f;
    float om = u ? 0.001f : 0.1f;
    const float* oldrow = (u ? emab : mainb) + (size_t)(c * MEMB + slot) * DIM;
    float* row = g_bankS[u][c * MEMB + slot];
    const float* sv = g_selvec[u][q];
    float v[8]; float ss = 0.f;
#pragma unroll
    for (int t = 0; t < 8; t++) {
        int d = lane + 32 * t;
        float x = m * oldrow[d] + om * sv[d];
        v[t] = x; ss += x * x;
    }
    ss = wred(ss);
    float inv = 1.f / fmaxf(sqrtf(ss), 1e-12f);
#pragma unroll
    for (int t = 0; t < 8; t++) row[lane + 32 * t] = v[t] * inv;
}

// ---------------------------------------------------------------------------
// K7: materialize contrast rows (f32 for possum + fp16 for GEMM).
// ---------------------------------------------------------------------------
__global__ void contrast_k() {
    int w = blockIdx.x * 8 + (threadIdx.x >> 5);
    int lane = threadIdx.x & 31;
    int u = w / NANC, q = w % NANC;
    int c = q >> 8, j = q & 255;
    const float* src = g_bankS[u][c * MEMB + g_samp[u][c][j]];
    float* dst = g_con[u][q];
    __half* dst16 = &g_B16[u][q * DIM];
#pragma unroll
    for (int t = 0; t < 8; t++) {
        int d = lane + 32 * t;
        float x = src[d];
        dst[d] = x;
        dst16[d] = __float2half(x);
    }
}

// ---------------------------------------------------------------------------
// K8: per-class positive-sum vectors.
// ---------------------------------------------------------------------------
__global__ void possum_k() {
    int u = blockIdx.x / NCLS, c = blockIdx.x % NCLS;
    int d = threadIdx.x;
    float s = 0.f;
    for (int j = 0; j < MV; j++) s += g_con[u][c * MV + j][d];
    g_psum[u][c][d] = s;
}

// ---------------------------------------------------------------------------
// K9: mma.sync fp16 GEMM + fused exp-rowsum.
// CTA: 128x128 tile, 8 warps (2m x 4n), each warp 64x32.
// K in 4 chunks of 64: 3-stage cp.async ring + explicit fragment double
// buffering inside each chunk so HMMA issue is never ld-dependent.
// smem rows padded to 72 halves (144B -> conflict-free ldmatrix).
// ---------------------------------------------------------------------------
#define KC 64
#define ROWP 72                         // halves per padded row
#define TILE_H (128 * ROWP)             // halves per matrix per stage
#define NSTAGE 3
#define GEMM_SMEM (NSTAGE * 2 * TILE_H * 2)   // 110592 bytes

__device__ __forceinline__ void ldsm_x4(uint32_t addr, uint32_t* r) {
    asm volatile("ldmatrix.sync.aligned.m8n8.x4.shared.b16 {%0,%1,%2,%3}, [%4];"
                 : "=r"(r[0]), "=r"(r[1]), "=r"(r[2]), "=r"(r[3]) : "r"(addr));
}
__device__ __forceinline__ void ldsm_x2(uint32_t addr, uint32_t* r) {
    asm volatile("ldmatrix.sync.aligned.m8n8.x2.shared.b16 {%0,%1}, [%2];"
                 : "=r"(r[0]), "=r"(r[1]) : "r"(addr));
}
__device__ __forceinline__ void mma16816(float* c, const uint32_t* a, const uint32_t* b) {
    asm volatile(
        "mma.sync.aligned.m16n8k16.row.col.f32.f16.f16.f32 "
        "{%0,%1,%2,%3}, {%4,%5,%6,%7}, {%8,%9}, {%0,%1,%2,%3};"
        : "+f"(c[0]), "+f"(c[1]), "+f"(c[2]), "+f"(c[3])
        : "r"(a[0]), "r"(a[1]), "r"(a[2]), "r"(a[3]), "r"(b[0]), "r"(b[1]));
}

// load one 128x64 fp16 tile into padded smem via cp.async (16B segments)
__device__ __forceinline__ void load_tile(uint32_t dbase, const __half* __restrict__ src,
                                          int gRowBase, int kc, int tid) {
#pragma unroll
    for (int r = 0; r < 4; r++) {
        int s = tid + r * 256;          // 0..1023
        int row = s >> 3;
        int c16 = s & 7;
        const __half* g = src + (size_t)(gRowBase + row) * DIM + kc * KC + c16 * 8;
        uint32_t d = dbase + row * (ROWP * 2) + c16 * 16;
        asm volatile("cp.async.cg.shared.global [%0], [%1], 16;" :: "r"(d), "l"(g) : "memory");
    }
}

__global__ void __launch_bounds__(256) gemm_mma() {
    extern __shared__ __half smh[];
    uint32_t sbase = smem_u32(smh);
    __shared__ float red[128][5];

    const int u = blockIdx.z;
    const int rowBase = blockIdx.y * 128;
    const int colBase = blockIdx.x * 128;
    int tid = threadIdx.x, w = tid >> 5, lane = tid & 31;
    int wm = w >> 2, wn = w & 3;           // warp 2x4 grid

    uint32_t stA[NSTAGE], stB[NSTAGE];
#pragma unroll
    for (int s = 0; s < NSTAGE; s++) {
        stA[s] = sbase + (uint32_t)(s * 2 * TILE_H * 2);
        stB[s] = stA[s] + (uint32_t)(TILE_H * 2);
    }

    const __half* A = g_A16;
    const __half* B = g_B16[u];

    float c[4][4][4];
#pragma unroll
    for (int mt = 0; mt < 4; mt++)
#pragma unroll
        for (int nt = 0; nt < 4; nt++)
#pragma unroll
            for (int e = 0; e < 4; e++) c[mt][nt][e] = 0.f;

    // prologue: fill 3 stages with chunks 0..2
#pragma unroll
    for (int s = 0; s < NSTAGE; s++) {
        load_tile(stA[s], A, rowBase, s, tid);
        load_tile(stB[s], B, colBase, s, tid);
        asm volatile("cp.async.commit_group;" ::: "memory");
    }

    // lane pieces for fragment addressing
    int aRow = wm * 64 + (lane & 15);
    int aColOff = ((lane >> 4) << 3);
    int bRow = wn * 32 + (lane & 7);
    int bColOff = (((lane >> 3) & 1) << 3);

    uint32_t a[2][4][4], b[2][4][2];

#pragma unroll
    for (int i = 0; i < 4; i++) {
        asm volatile("cp.async.wait_group %0;" :: "n"(NSTAGE - 1) : "memory");
        __syncthreads();
        const int st = i % NSTAGE;

        // preload kk=0 fragments
#pragma unroll
        for (int mt = 0; mt < 4; mt++)
            ldsm_x4(stA[st] + (uint32_t)((aRow + mt * 16) * (ROWP * 2) + aColOff * 2), a[0][mt]);
#pragma unroll
        for (int nt = 0; nt < 4; nt++)
            ldsm_x2(stB[st] + (uint32_t)((bRow + nt * 8) * (ROWP * 2) + bColOff * 2), b[0][nt]);

#pragma unroll
        for (int kk = 0; kk < 4; kk++) {
            const int cur = kk & 1, nxt = cur ^ 1;
            if (kk < 3) {
#pragma unroll
                for (int mt = 0; mt < 4; mt++)
                    ldsm_x4(stA[st] + (uint32_t)((aRow + mt * 16) * (ROWP * 2)
                          + ((kk + 1) * 16 + aColOff) * 2), a[nxt][mt]);
#pragma unroll
                for (int nt = 0; nt < 4; nt++)
                    ldsm_x2(stB[st] + (uint32_t)((bRow + nt * 8) * (ROWP * 2)
                          + ((kk + 1) * 16 + bColOff) * 2), b[nxt][nt]);
            }
#pragma unroll
            for (int mt = 0; mt < 4; mt++)
#pragma unroll
                for (int nt = 0; nt < 4; nt++)
                    mma16816(c[mt][nt], a[cur][mt], b[cur][nt]);
        }
        __syncthreads();
        if (i + NSTAGE < 4) {
            load_tile(stA[st], A, rowBase, i + NSTAGE, tid);
            load_tile(stB[st], B, colBase, i + NSTAGE, tid);
        }
        asm volatile("cp.async.commit_group;" ::: "memory");
    }

    // epilogue: per-row sum of exp(10*d) over this CTA's 128 columns
#pragma unroll
    for (int mt = 0; mt < 4; mt++) {
        float s0 = 0.f, s1 = 0.f;
#pragma unroll
        for (int nt = 0; nt < 4; nt++) {
            s0 += __expf(10.f * c[mt][nt][0]) + __expf(10.f * c[mt][nt][1]);
            s1 += __expf(10.f * c[mt][nt][2]) + __expf(10.f * c[mt][nt][3]);
        }
        s0 += __shfl_xor_sync(0xffffffffu, s0, 1);
        s0 += __shfl_xor_sync(0xffffffffu, s0, 2);
        s1 += __shfl_xor_sync(0xffffffffu, s1, 1);
        s1 += __shfl_xor_sync(0xffffffffu, s1, 2);
        if ((lane & 3) == 0) {
            int r0 = wm * 64 + mt * 16 + (lane >> 2);
            red[r0][wn] = s0;
            red[r0 + 8][wn] = s1;
        }
    }
    __syncthreads();
    if (tid < 128) {
        float s = red[tid][0] + red[tid][1] + red[tid][2] + red[tid][3];
        g_part[u][blockIdx.x][rowBase + tid] = s;
    }
}

// ---------------------------------------------------------------------------
// K10: per-anchor plp = 10*posdot/256 - log(sum_partials). Warp per anchor.
// ---------------------------------------------------------------------------
__global__ void reduce_plp() {
    int w = blockIdx.x * 8 + (threadIdx.x >> 5);
    int lane = threadIdx.x & 31;
    int u = w / NANC, i = w % NANC;
    int c = i >> 8;
    float pd = 0.f;
#pragma unroll
    for (int t = 0; t < 8; t++) {
        int d = lane + 32 * t;
        pd += g_anch[i][d] * g_psum[u][c][d];
    }
    pd = wred(pd);
    float s = 0.f;
    for (int t = lane; t < NTIL; t += 32) s += g_part[u][t][i];
    s = wred(s);
    if (lane == 0)
        g_plp[u][i] = pd * (10.f / 256.f) - logf(s);
}

// ---------------------------------------------------------------------------
// K11: final scalar.
// ---------------------------------------------------------------------------
__global__ void final_k(float* out) {
    __shared__ double sm[256];
    double s = 0.0;
    const float* p = &g_plp[0][0];
    for (int i = threadIdx.x; i < 2 * NANC; i += 256) s += (double)p[i];
    sm[threadIdx.x] = s;
    __syncthreads();
    for (int st = 128; st > 0; st >>= 1) {
        if (threadIdx.x < st) sm[threadIdx.x] += sm[threadIdx.x + st];
        __syncthreads();
    }
    if (threadIdx.x == 0) out[0] = (float)(-sm[0] / 10240.0);
}

// ---------------------------------------------------------------------------
extern "C" void kernel_launch(void* const* d_in, const int* in_sizes, int n_in,
                              void* d_out, int out_size) {
    (void)in_sizes; (void)n_in; (void)out_size;
    const float* main_proj = (const float*)d_in[0];
    const int*   main_gt   = (const int*)d_in[1];
    const float* aux_proj  = (const float*)d_in[2];
    const int*   aux_gt    = (const int*)d_in[3];
    const float* ema_bank  = (const float*)d_in[4];
    const float* main_bank = (const float*)d_in[5];
    float* out = (float*)d_out;

    unsigned ks[5][2];
    for (unsigned j = 0; j < 5; j++) tf2x32(0u, 42u, 0u, j, ks[j][0], ks[j][1]);
    unsigned k1m[2], k2m[2], k1e[2], k2e[2];
    tf2x32(ks[0][0], ks[0][1], 0u, 0u, k1m[0], k1m[1]);
    tf2x32(ks[0][0], ks[0][1], 0u, 1u, k2m[0], k2m[1]);
    tf2x32(ks[1][0], ks[1][1], 0u, 0u, k1e[0], k1e[1]);
    tf2x32(ks[1][0], ks[1][1], 0u, 1u, k2e[0], k2e[1]);

    cudaFuncSetAttribute(gemm_mma, cudaFuncAttributeMaxDynamicSharedMemorySize, GEMM_SMEM);

    select_k<<<60, 1024>>>(main_gt, aux_gt,
                           k1m[0], k1m[1], k1e[0], k1e[1], ks[2][0], ks[2][1]);
    perm_k<<<40, 256>>>(k2m[0], k2m[1], k2e[0], k2e[1]);
    samp_k<<<40, 256>>>(ks[4][0], ks[4][1], ks[3][0], ks[3][1]);
    gather_norm<<<3200, 256>>>(main_proj, aux_proj);
    update_k<<<2560, 256>>>(main_bank, ema_bank);
    contrast_k<<<1280, 256>>>();
    possum_k<<<40, 256>>>();
    gemm_mma<<<dim3(NTIL, NTIL, 2), 256, GEMM_SMEM>>>();
    reduce_plp<<<1280, 256>>>();
    final_k<<<1, 256>>>(out);
}

// round 11
// speedup vs baseline: 4.0870x; 1.0605x over previous
#include <cuda_runtime.h>
#include <cuda_fp16.h>
#include <cstdint>
#include <stdint.h>
#include <math.h>

// ---------------------------------------------------------------------------
// MemoryBankContrastLoss — JAX-threefry-exact pipeline, mma.sync (HMMA) GEMM.
// u==0 -> main, u==1 -> ema.  Gather inverted to coalesced scan + scatter.
// ---------------------------------------------------------------------------

#define NCLS 20
#define MEMB 512
#define MV   256
#define DIM  256
#define NANC 5120    // 20*256 anchors
#define NSEL 10240   // 20*512 selections per modality
#define PTOT 65536   // pixels per modality
#define NTIL 40      // 5120/128 col tiles per GEMM dimension

// ------------------------------ scratch ------------------------------------
__device__ unsigned       g_mask[2][PTOT / 32];      // pixel selected? (any role)
__device__ unsigned short g_msel[2][PTOT];           // sel slot + 1 (0 = none)
__device__ unsigned short g_manc[2][PTOT];           // anchor slot + 1
__device__ int   g_pinv  [2][NCLS][MEMB];            // inverse slot permutation
__device__ int   g_samp  [2][NCLS][MV];
__device__ float g_selvec[2][NSEL][DIM];             // RAW gathered feats
__device__ float g_anch  [NANC][DIM];                // raw then normalized in place
__device__ float g_con   [2][NANC][DIM];
__device__ float g_psum  [2][NCLS][DIM];
__device__ float g_part  [2][NTIL][NANC];
__device__ float g_plp   [2][NANC];

// fp16 copies for the tensor-core GEMM
__device__ __align__(16) __half g_A16[NANC*DIM];
__device__ __align__(16) __half g_B16[2][NANC*DIM];

// ------------------------------ threefry -----------------------------------
__host__ __device__ __forceinline__ void tf2x32(unsigned k0, unsigned k1,
                                                unsigned c0, unsigned c1,
                                                unsigned& o0, unsigned& o1) {
    unsigned ks0 = k0, ks1 = k1, ks2 = k0 ^ k1 ^ 0x1BD11BDAu;
    unsigned x0 = c0 + ks0, x1 = c1 + ks1;
#define TFRND(r) { x0 += x1; x1 = (x1 << r) | (x1 >> (32 - r)); x1 ^= x0; }
    TFRND(13) TFRND(15) TFRND(26) TFRND(6)   x0 += ks1; x1 += ks2 + 1u;
    TFRND(17) TFRND(29) TFRND(16) TFRND(24)  x0 += ks2; x1 += ks0 + 2u;
    TFRND(13) TFRND(15) TFRND(26) TFRND(6)   x0 += ks0; x1 += ks1 + 3u;
    TFRND(17) TFRND(29) TFRND(16) TFRND(24)  x0 += ks1; x1 += ks2 + 4u;
    TFRND(13) TFRND(15) TFRND(26) TFRND(6)   x0 += ks2; x1 += ks0 + 5u;
#undef TFRND
    o0 = x0; o1 = x1;
}

__host__ __device__ __forceinline__ unsigned tfx(unsigned k0, unsigned k1, unsigned ctr) {
    unsigned a, b;
    tf2x32(k0, k1, 0u, ctr, a, b);
    return a ^ b;
}

// ------------------------------ helpers ------------------------------------
__device__ __forceinline__ float wred(float v) {
#pragma unroll
    for (int o = 16; o > 0; o >>= 1) v += __shfl_xor_sync(0xffffffffu, v, o);
    return v;
}

__device__ __forceinline__ void bitonic(unsigned long long* a, int n, int tid, int nt) {
    for (int size = 2; size <= n; size <<= 1) {
        for (int stride = size >> 1; stride > 0; stride >>= 1) {
            __syncthreads();
            for (int i = tid; i < (n >> 1); i += nt) {
                int pos = 2 * i - (i & (stride - 1));
                bool up = ((pos & size) == 0);
                unsigned long long x = a[pos], y = a[pos + stride];
                if ((x > y) == up) { a[pos] = y; a[pos + stride] = x; }
            }
        }
    }
    __syncthreads();
}

__device__ __forceinline__ uint32_t smem_u32(const void* p) {
    uint32_t a;
    asm("{ .reg .u64 t; cvta.to.shared.u64 t, %1; cvt.u32.u64 %0, t; }" : "=r"(a) : "l"(p));
    return a;
}

// ---------------------------------------------------------------------------
// K0: zero masks + dest maps (must run every call: graph replays).
// ---------------------------------------------------------------------------
__global__ void init_maps() {
    int g = blockIdx.x * blockDim.x + threadIdx.x;
    int stride = gridDim.x * blockDim.x;
    for (int i = g; i < 2 * PTOT / 32; i += stride) (&g_mask[0][0])[i] = 0u;
    unsigned* ms = (unsigned*)&g_msel[0][0];
    unsigned* ma = (unsigned*)&g_manc[0][0];
    for (int i = g; i < 2 * PTOT / 2; i += stride) { ms[i] = 0u; ma[i] = 0u; }
}

// ---------------------------------------------------------------------------
// K1: merged selection kernel.
// blocks 0..59   : top-k pixel selection (task0 main-sel, task1 ema-sel,
//                  task2 anchors) -> scatter dest maps + mask
// blocks 60..99  : slot permutations -> g_pinv
// blocks 100..139: bank sampling -> g_samp
// ---------------------------------------------------------------------------
__global__ void __launch_bounds__(1024) sel3(
        const int* __restrict__ mgt, const int* __restrict__ agt,
        unsigned km0, unsigned km1, unsigned ke0, unsigned ke1,
        unsigned ka0, unsigned ka1,
        unsigned k2m0, unsigned k2m1, unsigned k2e0, unsigned k2e1,
        unsigned ksm0, unsigned ksm1, unsigned kse0, unsigned kse1) {
    int bid = blockIdx.x, tid = threadIdx.x;

    if (bid < 60) {
        int task = bid / NCLS, c = bid % NCLS;
        int N = (task == 2) ? 131072 : 65536;
        int k = (task == 2) ? MV : MEMB;
        unsigned K0 = (task == 0) ? km0 : (task == 1) ? ke0 : ka0;
        unsigned K1 = (task == 0) ? km1 : (task == 1) ? ke1 : ka1;

        __shared__ int hist[1024];
        __shared__ unsigned long long cand[2048];
        __shared__ int s_cnt, s_cut;

        hist[tid] = 0;
        __syncthreads();

        unsigned base = (unsigned)c * (unsigned)N;
        int iters = N >> 12;
        for (int it = 0; it < iters; it++) {
            int i0 = (it << 12) + (tid << 2);
            const int* src = (task == 0) ? mgt : (task == 1) ? agt
                           : (i0 < 65536 ? mgt : agt);
            int off = (task == 2 && i0 >= 65536) ? i0 - 65536 : i0;
            int4 l4 = *(const int4*)(src + off);
            int ls[4] = { l4.x, l4.y, l4.z, l4.w };
#pragma unroll
            for (int j = 0; j < 4; j++) {
                if (ls[j] == c) {
                    unsigned bits = tfx(K0, K1, base + (unsigned)(i0 + j));
                    atomicAdd(&hist[bits >> 22], 1);
                }
            }
        }
        __syncthreads();
        if (tid == 0) {
            int cum = 0, cut = 1023;
            for (int b = 0; b < 1024; b++) { cum += hist[b]; if (cum >= k) { cut = b; break; } }
            s_cut = cut; s_cnt = 0;
        }
        __syncthreads();
        unsigned cut = (unsigned)s_cut;
        for (int it = 0; it < iters; it++) {
            int i0 = (it << 12) + (tid << 2);
            const int* src = (task == 0) ? mgt : (task == 1) ? agt
                           : (i0 < 65536 ? mgt : agt);
            int off = (task == 2 && i0 >= 65536) ? i0 - 65536 : i0;
            int4 l4 = *(const int4*)(src + off);
            int ls[4] = { l4.x, l4.y, l4.z, l4.w };
#pragma unroll
            for (int j = 0; j < 4; j++) {
                if (ls[j] == c) {
                    unsigned bits = tfx(K0, K1, base + (unsigned)(i0 + j));
                    if ((bits >> 22) <= cut) {
                        int p = atomicAdd(&s_cnt, 1);
                        if (p < 2048)
                            cand[p] = ((unsigned long long)(bits >> 9) << 32) | (unsigned)(i0 + j);
                    }
                }
            }
        }
        __syncthreads();
        int cnt = min(s_cnt, 2048);
        for (int i = cnt + tid; i < 2048; i += 1024) cand[i] = 0xFFFFFFFFFFFFFFFFull;
        bitonic(cand, 2048, tid, 1024);

        // scatter dest maps
        for (int j = tid; j < k; j += 1024) {
            int idx = (int)(cand[j] & 0xFFFFFFFFu);
            if (task == 0) {
                g_msel[0][idx] = (unsigned short)(c * MEMB + j + 1);
                atomicOr(&g_mask[0][idx >> 5], 1u << (idx & 31));
            } else if (task == 1) {
                g_msel[1][idx] = (unsigned short)(c * MEMB + j + 1);
                atomicOr(&g_mask[1][idx >> 5], 1u << (idx & 31));
            } else {
                unsigned short a = (unsigned short)(c * MV + j + 1);
                if (idx < 65536) {
                    g_manc[0][idx] = a;
                    atomicOr(&g_mask[0][idx >> 5], 1u << (idx & 31));
                } else {
                    int p = idx - 65536;
                    g_manc[1][p] = a;
                    atomicOr(&g_mask[1][p >> 5], 1u << (p & 31));
                }
            }
        }
    } else if (bid < 100) {
        int q = bid - 60;
        int u = q / NCLS, c = q % NCLS;
        unsigned a0, a1, b0, b1;
        tf2x32(u ? k2e0 : k2m0, u ? k2e1 : k2m1, 0u, (unsigned)c, a0, a1);
        tf2x32(a0, a1, 0u, 1u, b0, b1);
        __shared__ unsigned long long arr[512];
        for (int j = tid; j < 512; j += 1024) {
            unsigned bits = tfx(b0, b1, (unsigned)j);
            arr[j] = ((unsigned long long)bits << 32) | (unsigned)j;
        }
        bitonic(arr, 512, tid, 1024);
        for (int j = tid; j < 512; j += 1024) {
            int slot = (int)(arr[j] & 0xFFFFFFFFu);
            g_pinv[u][c][slot] = j;
        }
    } else {
        int q = bid - 100;
        int u = q / NCLS, c = q % NCLS;
        unsigned K0 = u ? kse0 : ksm0, K1 = u ? kse1 : ksm1;
        __shared__ unsigned long long arr[512];
        for (int j = tid; j < 512; j += 1024) {
            unsigned bits = tfx(K0, K1, (unsigned)(c * 512 + j));
            arr[j] = ((unsigned long long)(bits >> 9) << 32) | (unsigned)j;
        }
        bitonic(arr, 512, tid, 1024);
        for (int j = tid; j < MV; j += 1024)
            g_samp[u][c][j] = (int)(arr[j] & 0xFFFFFFFFu);
    }
}

// ---------------------------------------------------------------------------
// K2: coalesced scan of both projections; scatter RAW values of selected
// pixels into g_selvec / g_anch. Reads only masked 4-pixel groups.
// ---------------------------------------------------------------------------
__global__ void scan_scatter(const float* __restrict__ mainp,
                             const float* __restrict__ auxp) {
    const int total = 2 * 4 * 256 * 4096;   // float4 groups
    int g = blockIdx.x * blockDim.x + threadIdx.x;
    int stride = gridDim.x * blockDim.x;
    for (int i = g; i < total; i += stride) {
        int s4 = i & 4095;
        int c  = (i >> 12) & 255;
        int b  = (i >> 20) & 3;
        int m  = i >> 22;
        int s  = s4 << 2;
        int pix = (b << 14) + s;
        unsigned nib = (g_mask[m][pix >> 5] >> (pix & 31)) & 0xFu;
        if (!nib) continue;
        const float* src = m ? auxp : mainp;
        float4 v = *(const float4*)(src + (((size_t)(b * 256 + c)) << 14) + s);
        ushort4 sl = *(const ushort4*)&g_msel[m][pix];
        ushort4 an = *(const ushort4*)&g_manc[m][pix];
        float vv[4] = { v.x, v.y, v.z, v.w };
        unsigned short sls[4] = { sl.x, sl.y, sl.z, sl.w };
        unsigned short ans[4] = { an.x, an.y, an.z, an.w };
#pragma unroll
        for (int e = 0; e < 4; e++) {
            if ((nib >> e) & 1u) {
                if (sls[e]) g_selvec[m][sls[e] - 1][c] = vv[e];
                if (ans[e]) g_anch[ans[e] - 1][c] = vv[e];
            }
        }
    }
}

// ---------------------------------------------------------------------------
// K3: normalize anchors in place + write fp16 copy. Warp per anchor row.
// ---------------------------------------------------------------------------
__global__ void norm_anch() {
    int w = blockIdx.x * 8 + (threadIdx.x >> 5);
    int lane = threadIdx.x & 31;
    float* row = g_anch[w];
    __half* row16 = &g_A16[w * DIM];
    float v[8]; float ss = 0.f;
#pragma unroll
    for (int t = 0; t < 8; t++) {
        v[t] = row[lane + 32 * t];
        ss += v[t] * v[t];
    }
    ss = wred(ss);
    float inv = 1.f / fmaxf(sqrtf(ss), 1e-12f);
#pragma unroll
    for (int t = 0; t < 8; t++) {
        float x = v[t] * inv;
        row[lane + 32 * t] = x;
        row16[lane + 32 * t] = __float2half(x);
    }
}

// ---------------------------------------------------------------------------
// K4: fused bank-update + contrast materialization. Only the 256 sampled
// slots per (u, class) are ever read downstream, so only those are computed:
//   con = l2norm(m*old[slot] + (1-m)*l2norm(feat[pinv[slot]]))
// Warp per sampled row (2*20*256 = 10240 warps).
// ---------------------------------------------------------------------------
__global__ void upd_con(const float* __restrict__ mainb,
                        const float* __restrict__ emab) {
    int w = blockIdx.x * 8 + (threadIdx.x >> 5);
    int lane = threadIdx.x & 31;
    int u = w / NANC, q = w % NANC;
    int c = q >> 8, jv = q & 255;
    int slot = g_samp[u][c][jv];
    int j = g_pinv[u][c][slot];
    float m  = u ? 0.999f : 0.9f;
    float om = u ? 0.001f : 0.1f;
    const float* oldrow = (u ? emab : mainb) + (size_t)(c * MEMB + slot) * DIM;
    const float* feat = g_selvec[u][c * MEMB + j];
    float f[8], o[8];
    float ssf = 0.f;
#pragma unroll
    for (int t = 0; t < 8; t++) {
        int d = lane + 32 * t;
        f[t] = feat[d]; o[t] = oldrow[d];
        ssf += f[t] * f[t];
    }
    ssf = wred(ssf);
    float invf = 1.f / fmaxf(sqrtf(ssf), 1e-12f);
    float x[8]; float ss = 0.f;
#pragma unroll
    for (int t = 0; t < 8; t++) {
        float y = m * o[t] + om * (f[t] * invf);
        x[t] = y; ss += y * y;
    }
    ss = wred(ss);
    float inv = 1.f / fmaxf(sqrtf(ss), 1e-12f);
    float* dst = g_con[u][q];
    __half* dst16 = &g_B16[u][q * DIM];
#pragma unroll
    for (int t = 0; t < 8; t++) {
        int d = lane + 32 * t;
        float y = x[t] * inv;
        dst[d] = y;
        dst16[d] = __float2half(y);
    }
}

// ---------------------------------------------------------------------------
// K5: per-class positive-sum vectors.
// ---------------------------------------------------------------------------
__global__ void possum_k() {
    int u = blockIdx.x / NCLS, c = blockIdx.x % NCLS;
    int d = threadIdx.x;
    float s = 0.f;
    for (int j = 0; j < MV; j++) s += g_con[u][c * MV + j][d];
    g_psum[u][c][d] = s;
}

// ---------------------------------------------------------------------------
// K6: mma.sync fp16 GEMM + fused exp-rowsum (unchanged from R10 winner).
// ---------------------------------------------------------------------------
#define KC 64
#define ROWP 72
#define TILE_H (128 * ROWP)
#define NSTAGE 3
#define GEMM_SMEM (NSTAGE * 2 * TILE_H * 2)

__device__ __forceinline__ void ldsm_x4(uint32_t addr, uint32_t* r) {
    asm volatile("ldmatrix.sync.aligned.m8n8.x4.shared.b16 {%0,%1,%2,%3}, [%4];"
                 : "=r"(r[0]), "=r"(r[1]), "=r"(r[2]), "=r"(r[3]) : "r"(addr));
}
__device__ __forceinline__ void ldsm_x2(uint32_t addr, uint32_t* r) {
    asm volatile("ldmatrix.sync.aligned.m8n8.x2.shared.b16 {%0,%1}, [%2];"
                 : "=r"(r[0]), "=r"(r[1]) : "r"(addr));
}
__device__ __forceinline__ void mma16816(float* c, const uint32_t* a, const uint32_t* b) {
    asm volatile(
        "mma.sync.aligned.m16n8k16.row.col.f32.f16.f16.f32 "
        "{%0,%1,%2,%3}, {%4,%5,%6,%7}, {%8,%9}, {%0,%1,%2,%3};"
        : "+f"(c[0]), "+f"(c[1]), "+f"(c[2]), "+f"(c[3])
        : "r"(a[0]), "r"(a[1]), "r"(a[2]), "r"(a[3]), "r"(b[0]), "r"(b[1]));
}

__device__ __forceinline__ void load_tile(uint32_t dbase, const __half* __restrict__ src,
                                          int gRowBase, int kc, int tid) {
#pragma unroll
    for (int r = 0; r < 4; r++) {
        int s = tid + r * 256;
        int row = s >> 3;
        int c16 = s & 7;
        const __half* g = src + (size_t)(gRowBase + row) * DIM + kc * KC + c16 * 8;
        uint32_t d = dbase + row * (ROWP * 2) + c16 * 16;
        asm volatile("cp.async.cg.shared.global [%0], [%1], 16;" :: "r"(d), "l"(g) : "memory");
    }
}

__global__ void __launch_bounds__(256) gemm_mma() {
    extern __shared__ __half smh[];
    uint32_t sbase = smem_u32(smh);
    __shared__ float red[128][5];

    const int u = blockIdx.z;
    const int rowBase = blockIdx.y * 128;
    const int colBase = blockIdx.x * 128;
    int tid = threadIdx.x, w = tid >> 5, lane = tid & 31;
    int wm = w >> 2, wn = w & 3;

    uint32_t stA[NSTAGE], stB[NSTAGE];
#pragma unroll
    for (int s = 0; s < NSTAGE; s++) {
        stA[s] = sbase + (uint32_t)(s * 2 * TILE_H * 2);
        stB[s] = stA[s] + (uint32_t)(TILE_H * 2);
    }

    const __half* A = g_A16;
    const __half* B = g_B16[u];

    float c[4][4][4];
#pragma unroll
    for (int mt = 0; mt < 4; mt++)
#pragma unroll
        for (int nt = 0; nt < 4; nt++)
#pragma unroll
            for (int e = 0; e < 4; e++) c[mt][nt][e] = 0.f;

#pragma unroll
    for (int s = 0; s < NSTAGE; s++) {
        load_tile(stA[s], A, rowBase, s, tid);
        load_tile(stB[s], B, colBase, s, tid);
        asm volatile("cp.async.commit_group;" ::: "memory");
    }

    int aRow = wm * 64 + (lane & 15);
    int aColOff = ((lane >> 4) << 3);
    int bRow = wn * 32 + (lane & 7);
    int bColOff = (((lane >> 3) & 1) << 3);

    uint32_t a[2][4][4], b[2][4][2];

#pragma unroll
    for (int i = 0; i < 4; i++) {
        asm volatile("cp.async.wait_group %0;" :: "n"(NSTAGE - 1) : "memory");
        __syncthreads();
        const int st = i % NSTAGE;

#pragma unroll
        for (int mt = 0; mt < 4; mt++)
            ldsm_x4(stA[st] + (uint32_t)((aRow + mt * 16) * (ROWP * 2) + aColOff * 2), a[0][mt]);
#pragma unroll
        for (int nt = 0; nt < 4; nt++)
            ldsm_x2(stB[st] + (uint32_t)((bRow + nt * 8) * (ROWP * 2) + bColOff * 2), b[0][nt]);

#pragma unroll
        for (int kk = 0; kk < 4; kk++) {
            const int cur = kk & 1, nxt = cur ^ 1;
            if (kk < 3) {
#pragma unroll
                for (int mt = 0; mt < 4; mt++)
                    ldsm_x4(stA[st] + (uint32_t)((aRow + mt * 16) * (ROWP * 2)
                          + ((kk + 1) * 16 + aColOff) * 2), a[nxt][mt]);
#pragma unroll
                for (int nt = 0; nt < 4; nt++)
                    ldsm_x2(stB[st] + (uint32_t)((bRow + nt * 8) * (ROWP * 2)
                          + ((kk + 1) * 16 + bColOff) * 2), b[nxt][nt]);
            }
#pragma unroll
            for (int mt = 0; mt < 4; mt++)
#pragma unroll
                for (int nt = 0; nt < 4; nt++)
                    mma16816(c[mt][nt], a[cur][mt], b[cur][nt]);
        }
        __syncthreads();
        if (i + NSTAGE < 4) {
            load_tile(stA[st], A, rowBase, i + NSTAGE, tid);
            load_tile(stB[st], B, colBase, i + NSTAGE, tid);
        }
        asm volatile("cp.async.commit_group;" ::: "memory");
    }

#pragma unroll
    for (int mt = 0; mt < 4; mt++) {
        float s0 = 0.f, s1 = 0.f;
#pragma unroll
        for (int nt = 0; nt < 4; nt++) {
            s0 += __expf(10.f * c[mt][nt][0]) + __expf(10.f * c[mt][nt][1]);
            s1 += __expf(10.f * c[mt][nt][2]) + __expf(10.f * c[mt][nt][3]);
        }
        s0 += __shfl_xor_sync(0xffffffffu, s0, 1);
        s0 += __shfl_xor_sync(0xffffffffu, s0, 2);
        s1 += __shfl_xor_sync(0xffffffffu, s1, 1);
        s1 += __shfl_xor_sync(0xffffffffu, s1, 2);
        if ((lane & 3) == 0) {
            int r0 = wm * 64 + mt * 16 + (lane >> 2);
            red[r0][wn] = s0;
            red[r0 + 8][wn] = s1;
        }
    }
    __syncthreads();
    if (tid < 128) {
        float s = red[tid][0] + red[tid][1] + red[tid][2] + red[tid][3];
        g_part[u][blockIdx.x][rowBase + tid] = s;
    }
}

// ---------------------------------------------------------------------------
// K7: per-anchor plp = 10*posdot/256 - log(sum_partials). Warp per anchor.
// ---------------------------------------------------------------------------
__global__ void reduce_plp() {
    int w = blockIdx.x * 8 + (threadIdx.x >> 5);
    int lane = threadIdx.x & 31;
    int u = w / NANC, i = w % NANC;
    int c = i >> 8;
    float pd = 0.f;
#pragma unroll
    for (int t = 0; t < 8; t++) {
        int d = lane + 32 * t;
        pd += g_anch[i][d] * g_psum[u][c][d];
    }
    pd = wred(pd);
    float s = 0.f;
    for (int t = lane; t < NTIL; t += 32) s += g_part[u][t][i];
    s = wred(s);
    if (lane == 0)
        g_plp[u][i] = pd * (10.f / 256.f) - logf(s);
}

// ---------------------------------------------------------------------------
// K8: final scalar.
// ---------------------------------------------------------------------------
__global__ void final_k(float* out) {
    __shared__ double sm[256];
    double s = 0.0;
    const float* p = &g_plp[0][0];
    for (int i = threadIdx.x; i < 2 * NANC; i += 256) s += (double)p[i];
    sm[threadIdx.x] = s;
    __syncthreads();
    for (int st = 128; st > 0; st >>= 1) {
        if (threadIdx.x < st) sm[threadIdx.x] += sm[threadIdx.x + st];
        __syncthreads();
    }
    if (threadIdx.x == 0) out[0] = (float)(-sm[0] / 10240.0);
}

// ---------------------------------------------------------------------------
extern "C" void kernel_launch(void* const* d_in, const int* in_sizes, int n_in,
                              void* d_out, int out_size) {
    (void)in_sizes; (void)n_in; (void)out_size;
    const float* main_proj = (const float*)d_in[0];
    const int*   main_gt   = (const int*)d_in[1];
    const float* aux_proj  = (const float*)d_in[2];
    const int*   aux_gt    = (const int*)d_in[3];
    const float* ema_bank  = (const float*)d_in[4];
    const float* main_bank = (const float*)d_in[5];
    float* out = (float*)d_out;

    unsigned ks[5][2];
    for (unsigned j = 0; j < 5; j++) tf2x32(0u, 42u, 0u, j, ks[j][0], ks[j][1]);
    unsigned k1m[2], k2m[2], k1e[2], k2e[2];
    tf2x32(ks[0][0], ks[0][1], 0u, 0u, k1m[0], k1m[1]);
    tf2x32(ks[0][0], ks[0][1], 0u, 1u, k2m[0], k2m[1]);
    tf2x32(ks[1][0], ks[1][1], 0u, 0u, k1e[0], k1e[1]);
    tf2x32(ks[1][0], ks[1][1], 0u, 1u, k2e[0], k2e[1]);

    cudaFuncSetAttribute(gemm_mma, cudaFuncAttributeMaxDynamicSharedMemorySize, GEMM_SMEM);

    init_maps<<<132, 256>>>();
    sel3<<<140, 1024>>>(main_gt, aux_gt,
                        k1m[0], k1m[1], k1e[0], k1e[1], ks[2][0], ks[2][1],
                        k2m[0], k2m[1], k2e[0], k2e[1],
                        ks[4][0], ks[4][1], ks[3][0], ks[3][1]);
    scan_scatter<<<4096, 256>>>(main_proj, aux_proj);
    norm_anch<<<640, 256>>>();
    upd_con<<<1280, 256>>>(main_bank, ema_bank);
    possum_k<<<40, 256>>>();
    gemm_mma<<<dim3(NTIL, NTIL, 2), 256, GEMM_SMEM>>>();
    reduce_plp<<<1280, 256>>>();
    final_k<<<1, 256>>>(out);
}